// round 6
// baseline (speedup 1.0000x reference)
#include <cuda_runtime.h>

#define NBATCH  8
#define NCLASS  80
#define NBOX    32
#define NCH     (NBATCH * NCLASS)   // 640
#define THREADS 256
#define NCHUNK  3840
#define NPERSIST 1184               // 148 SMs * 8 blocks
#define LN2f    0.693147180559945f
#define SCALEf  (0.25f * LN2f)      // folds /4 (p=(1+t)/2 squared) and log2->ln

// Per (b,c) channel, 6 deterministic partial slots:
// slots 0..3 = 4 chunks of level0 (128x128), slot 4 = level1, slot 5 = level2.
// Every slot written every launch -> deterministic, no zeroing needed.
__device__ float g_pos[NCH][6];
__device__ float g_neg[NCH][6];
__device__ int   g_np [NCH][6];
__device__ int   g_arrive;   // zero-init; last block resets -> graph-replay safe
__device__ int   g_ticket;   // dynamic chunk ticket; last block resets

__device__ __forceinline__ float fast_tanh(float x) {
    float y; asm("tanh.approx.f32 %0, %1;" : "=f"(y) : "f"(x)); return y;
}
__device__ __forceinline__ float fast_lg2(float x) {
    float y; asm("lg2.approx.f32 %0, %1;" : "=f"(y) : "f"(x)); return y;
}

// ---- fast path: no boxes -> target==0 everywhere.
// contribution_ln = ln2 * (lg2(1-t) - 1) * (1+t)^2 / 4,  t = tanh(h/2)
// accumulate nA += lg2(1-t)*w^2, nB += w^2;  thread-end: nacc = SCALE*(nA-nB)
template<int NITER>
__device__ __forceinline__ void process_fast(const float4* __restrict__ hp,
                                             float& nA, float& nB)
{
    float4 v[NITER];
    #pragma unroll
    for (int i = 0; i < NITER; i++) v[i] = hp[threadIdx.x + i * THREADS];
    #pragma unroll
    for (int i = 0; i < NITER; i++) {
        float hv[4] = {v[i].x, v[i].y, v[i].z, v[i].w};
        #pragma unroll
        for (int e = 0; e < 4; e++) {
            float t = fast_tanh(hv[e] * 0.5f);
            float u = 1.0f - t;           // 2*(1-p)
            float w = 1.0f + t;           // 2*p
            float w2 = w * w;
            nA = fmaf(fast_lg2(u), w2, nA);
            nB += w2;
        }
    }
}

// ---- general path: on-the-fly windowed-gaussian scatter-max, branchless focal ----
template<int LOGW, int NITER>
__device__ __forceinline__ void process_box(const float4* __restrict__ hp, int base,
    int nb, const int* __restrict__ s_x, const int* __restrict__ s_y,
    const int* __restrict__ s_r2, const float* __restrict__ s_inv,
    float& pA, float& pB, float& nA, float& nB, int& npos)
{
    float4 v[NITER];
    #pragma unroll
    for (int i = 0; i < NITER; i++) v[i] = hp[threadIdx.x + i * THREADS];
    #pragma unroll
    for (int i = 0; i < NITER; i++) {
        int pi0 = base + ((threadIdx.x + i * THREADS) << 2);
        int y   = pi0 >> LOGW;            // 4 consecutive px share one row at all levels
        int x0  = pi0 & ((1 << LOGW) - 1);
        float hv[4] = {v[i].x, v[i].y, v[i].z, v[i].w};
        float g[4]  = {0.f, 0.f, 0.f, 0.f};
        for (int k = 0; k < nb; k++) {
            int dy  = y - s_y[k];
            int dy2 = dy * dy;
            int r2  = s_r2[k];
            if (dy2 <= r2) {                       // whole-quad row rejection
                float inv = s_inv[k];
                int bx = s_x[k];
                #pragma unroll
                for (int e = 0; e < 4; e++) {
                    int dx  = x0 + e - bx;
                    int dx2 = dx * dx;
                    if (dx2 <= r2) {               // |dx|<=r && |dy|<=r
                        float d2 = (float)(dx2 + dy2);
                        g[e] = fmaxf(g[e], __expf(-d2 * inv));  // expf(-0.0)==1.0 at center
                    }
                }
            }
        }
        #pragma unroll
        for (int e = 0; e < 4; e++) {
            float t = fast_tanh(hv[e] * 0.5f);
            float u = 1.0f - t;                    // 2*(1-p)
            float w = 1.0f + t;                    // 2*p
            bool pos = (g[e] == 1.0f);
            float omg = 1.0f - g[e];
            float g4 = omg * omg; g4 *= g4;        // (1-target)^4 (==1 when target==0)
            // pos: (lg2(w)-1)*u^2 ; neg: (lg2(u)-1)*w^2*g4  -> single lg2 via selects
            float arg = pos ? w : u;
            float s   = pos ? u : w;
            float m   = (s * s) * (pos ? 1.0f : g4);
            float l   = fast_lg2(arg) * m;
            if (pos) { pA += l; pB += m; npos++; }
            else     { nA += l; nB += m; }
        }
    }
}

__global__ __launch_bounds__(THREADS) void hough_main(
    const float* __restrict__ h0, const float* __restrict__ h1, const float* __restrict__ h2,
    const float* __restrict__ boxes, const int* __restrict__ labels,
    float* __restrict__ out)
{
    __shared__ int   s_cnt, s_chunk, s_last;
    __shared__ int   s_x[NBOX], s_y[NBOX], s_r2[NBOX];
    __shared__ float s_inv[NBOX];
    __shared__ float sp[8], sn[8];
    __shared__ int   si[8];

    int wid = threadIdx.x >> 5, lane = threadIdx.x & 31;
    int chunk = blockIdx.x;
    if (threadIdx.x == 0) s_cnt = 0;
    __syncthreads();

    while (chunk < NCHUNK) {
        // ---- decode chunk ----
        const float* heat; int chan, slot, W, base, cat;
        if (chunk < 2560)      { heat = h0; chan = chunk >> 2; int ck = chunk & 3; slot = ck;
                                 W = 128; base = ck * 4096; cat = 0; }
        else if (chunk < 3200) { heat = h1; chan = chunk - 2560; slot = 4; W = 64; base = 0; cat = 1; }
        else                   { heat = h2; chan = chunk - 3200; slot = 5; W = 32; base = 0; cat = 2; }
        int b = chan / NCLASS;
        int c = chan - b * NCLASS;

        // ---- gather boxes of batch b with label == c (order-independent: max only) ----
        if (threadIdx.x < NBOX) {
            int lab = labels[b * NBOX + threadIdx.x];
            if (lab == c) {
                const float* bp = boxes + (size_t)(b * NBOX + threadIdx.x) * 4;
                float Wf = (float)W;
                int x = (int)floorf(bp[0] * Wf);
                int y = (int)floorf(bp[1] * Wf);
                float s2 = bp[2] * Wf + bp[3] * Wf;
                int r = (int)floorf(s2 * 0.25f);    // /4.0 exact as *0.25f
                if (r < 1) r = 1;
                float sigma = (float)(2 * r + 1) * (1.0f / 6.0f);
                int k = atomicAdd(&s_cnt, 1);
                s_x[k] = x; s_y[k] = y; s_r2[k] = r * r;
                s_inv[k] = 1.0f / (2.0f * sigma * sigma);
            }
        }
        __syncthreads();
        int nb = s_cnt;

        const float4* hp = (const float4*)(heat + (size_t)chan * (W * W) + base);
        float pA = 0.f, pB = 0.f, nA = 0.f, nB = 0.f; int npos = 0;

        if (nb == 0) {
            if (cat == 2) process_fast<1>(hp, nA, nB);
            else          process_fast<4>(hp, nA, nB);
        } else {
            if (cat == 0)      process_box<7,4>(hp, base, nb, s_x, s_y, s_r2, s_inv, pA, pB, nA, nB, npos);
            else if (cat == 1) process_box<6,4>(hp, base, nb, s_x, s_y, s_r2, s_inv, pA, pB, nA, nB, npos);
            else               process_box<5,1>(hp, base, nb, s_x, s_y, s_r2, s_inv, pA, pB, nA, nB, npos);
        }

        float pacc = SCALEf * (pA - pB);   // ln2/4 * sum[(lg2(arg)-1)*m]
        float nacc = SCALEf * (nA - nB);

        // ---- deterministic block reduction ----
        #pragma unroll
        for (int o = 16; o > 0; o >>= 1) {
            pacc += __shfl_down_sync(0xffffffffu, pacc, o);
            nacc += __shfl_down_sync(0xffffffffu, nacc, o);
            npos += __shfl_down_sync(0xffffffffu, npos, o);
        }
        if (lane == 0) { sp[wid] = pacc; sn[wid] = nacc; si[wid] = npos; }
        __syncthreads();
        if (threadIdx.x == 0) {
            float P = 0.f, Ng = 0.f; int I = 0;
            #pragma unroll
            for (int i = 0; i < 8; i++) { P += sp[i]; Ng += sn[i]; I += si[i]; }
            g_pos[chan][slot] = P; g_neg[chan][slot] = Ng; g_np[chan][slot] = I;
            s_chunk = NPERSIST + atomicAdd(&g_ticket, 1);   // next work item
            s_cnt = 0;
        }
        __syncthreads();
        chunk = s_chunk;
    }

    // ---- arrival; last of NPERSIST blocks runs the fused epilogue ----
    if (threadIdx.x == 0) {
        __threadfence();
        int prev = atomicAdd(&g_arrive, 1);
        s_last = (prev == NPERSIST - 1);
    }
    __syncthreads();

    if (s_last) {
        float acc = 0.f;
        for (int ch = threadIdx.x; ch < NCH; ch += THREADS) {
            float pl = 0.f, nl = 0.f; int np = 0;
            #pragma unroll
            for (int s = 0; s < 6; s++) {
                pl += __ldcg(&g_pos[ch][s]);
                nl += __ldcg(&g_neg[ch][s]);
                np += __ldcg(&g_np [ch][s]);
            }
            float loss = (np == 0) ? (-nl) : (-(pl + nl) / (float)np);
            acc += fminf(loss, 10.0f);
        }
        #pragma unroll
        for (int o = 16; o > 0; o >>= 1) acc += __shfl_down_sync(0xffffffffu, acc, o);
        __shared__ float sa[8];
        if (lane == 0) sa[wid] = acc;
        __syncthreads();
        if (threadIdx.x == 0) {
            float tot = 0.f;
            #pragma unroll
            for (int i = 0; i < 8; i++) tot += sa[i];
            float mean = tot * (1.0f / (float)NCH);
            float lm = log1pf(mean);
            out[0] = lm / (1.0f + lm);
            g_arrive = 0;   // reset for next graph replay
            g_ticket = 0;
        }
    }
}

extern "C" void kernel_launch(void* const* d_in, const int* in_sizes, int n_in,
                              void* d_out, int out_size)
{
    const float* h0     = (const float*)d_in[0];   // [8,80,128,128]
    const float* h1     = (const float*)d_in[1];   // [8,80,64,64]
    const float* h2     = (const float*)d_in[2];   // [8,80,32,32]
    const float* boxes  = (const float*)d_in[3];   // [8,32,4]
    const int*   labels = (const int*)d_in[4];     // [8,32]
    // d_in[5] = image_sizes (int64) — cancels mathematically, unused.

    hough_main<<<NPERSIST, THREADS>>>(h0, h1, h2, boxes, labels, (float*)d_out);
}

// round 7
// speedup vs baseline: 1.0881x; 1.0881x over previous
#include <cuda_runtime.h>

#define NBATCH  8
#define NCLASS  80
#define NBOX    32
#define NCH     (NBATCH * NCLASS)   // 640
#define THREADS 256
#define NBLOCKS 3840
#define LN2f    0.693147180559945f
#define SCALEf  (0.25f * LN2f)      // folds /4 (from p=(1+t)/2 squared) and log2->ln

// Per (b,c) channel, 6 deterministic partial slots:
// slots 0..3 = 4 chunks of level0 (128x128), slot 4 = level1, slot 5 = level2.
// Every slot written every launch -> deterministic, no zeroing needed.
__device__ float g_pos[NCH][6];
__device__ float g_neg[NCH][6];
__device__ int   g_np [NCH][6];
__device__ int   g_arrive;   // zero-init; last block resets -> graph-replay safe

__device__ __forceinline__ float fast_tanh(float x) {
    float y; asm("tanh.approx.f32 %0, %1;" : "=f"(y) : "f"(x)); return y;
}
__device__ __forceinline__ float fast_lg2(float x) {
    float y; asm("lg2.approx.f32 %0, %1;" : "=f"(y) : "f"(x)); return y;
}

// ---- fast path: no boxes -> target==0 everywhere.
// per-pixel contribution_ln = ln2/4 * [(lg2(1-t) - 1) * (1+t)^2],  t = tanh(h/2)
// accumulate nA += lg2(1-t)*(1+t)^2 and nB += (1+t)^2; fold constants once per thread.
template<int NITER>
__device__ __forceinline__ void process_fast(const float4* __restrict__ hp,
                                             float& nA, float& nB)
{
    float4 v[NITER];
    #pragma unroll
    for (int i = 0; i < NITER; i++) v[i] = hp[threadIdx.x + i * THREADS];
    #pragma unroll
    for (int i = 0; i < NITER; i++) {
        float hv[4] = {v[i].x, v[i].y, v[i].z, v[i].w};
        #pragma unroll
        for (int e = 0; e < 4; e++) {
            float t = fast_tanh(hv[e] * 0.5f);
            float u = 1.0f - t;           // 2*(1-p)
            float w = 1.0f + t;           // 2*p
            float w2 = w * w;
            nA = fmaf(fast_lg2(u), w2, nA);
            nB += w2;
        }
    }
}

// ---- general path: on-the-fly windowed-gaussian scatter-max, single-lg2 focal ----
template<int LOGW, int NITER>
__device__ __forceinline__ void process_box(const float4* __restrict__ hp, int base,
    int nb, const int* __restrict__ s_x, const int* __restrict__ s_y,
    const int* __restrict__ s_r2, const float* __restrict__ s_inv,
    float& pA, float& pB, float& nA, float& nB, int& npos)
{
    float4 v[NITER];
    #pragma unroll
    for (int i = 0; i < NITER; i++) v[i] = hp[threadIdx.x + i * THREADS];
    #pragma unroll
    for (int i = 0; i < NITER; i++) {
        int pi0 = base + ((threadIdx.x + i * THREADS) << 2);
        int y   = pi0 >> LOGW;            // 4 consecutive px share one row at all levels
        int x0  = pi0 & ((1 << LOGW) - 1);
        float hv[4] = {v[i].x, v[i].y, v[i].z, v[i].w};
        float g[4]  = {0.f, 0.f, 0.f, 0.f};
        for (int k = 0; k < nb; k++) {
            int dy  = y - s_y[k];
            int dy2 = dy * dy;
            int r2  = s_r2[k];
            if (dy2 <= r2) {                       // whole-quad row rejection
                float inv = s_inv[k];
                int bx = s_x[k];
                #pragma unroll
                for (int e = 0; e < 4; e++) {
                    int dx  = x0 + e - bx;
                    int dx2 = dx * dx;
                    if (dx2 <= r2) {               // |dx|<=r && |dy|<=r
                        float d2 = (float)(dx2 + dy2);
                        g[e] = fmaxf(g[e], __expf(-d2 * inv));  // expf(-0.0)==1.0 at center
                    }
                }
            }
        }
        #pragma unroll
        for (int e = 0; e < 4; e++) {
            float t = fast_tanh(hv[e] * 0.5f);
            float u = 1.0f - t;                    // 2*(1-p)
            float w = 1.0f + t;                    // 2*p
            bool pos = (g[e] == 1.0f);
            float omg = 1.0f - g[e];
            float g4 = omg * omg; g4 *= g4;        // (1-target)^4 (==1 when target==0)
            // pos: (lg2(w)-1)*u^2 ; neg: (lg2(u)-1)*w^2*g4 ; single lg2 via selects
            float arg = pos ? w : u;
            float s   = pos ? u : w;
            float m   = (s * s) * (pos ? 1.0f : g4);
            float l   = fast_lg2(arg) * m;
            if (pos) { pA += l; pB += m; npos++; }
            else     { nA += l; nB += m; }
        }
    }
}

__global__ __launch_bounds__(THREADS, 8) void hough_main(
    const float* __restrict__ h0, const float* __restrict__ h1, const float* __restrict__ h2,
    const float* __restrict__ boxes, const int* __restrict__ labels,
    float* __restrict__ out)
{
    int blk = blockIdx.x;
    const float* heat; int chan, slot, W, base, cat;
    if (blk < 2560)      { heat = h0; chan = blk >> 2; int ck = blk & 3; slot = ck;
                           W = 128; base = ck * 4096; cat = 0; }
    else if (blk < 3200) { heat = h1; chan = blk - 2560; slot = 4; W = 64; base = 0; cat = 1; }
    else                 { heat = h2; chan = blk - 3200; slot = 5; W = 32; base = 0; cat = 2; }
    int b = chan / NCLASS;
    int c = chan - b * NCLASS;

    // ---- gather boxes of batch b with label == c (order-independent: max only) ----
    __shared__ int   s_cnt;
    __shared__ int   s_x[NBOX], s_y[NBOX], s_r2[NBOX];
    __shared__ float s_inv[NBOX];
    if (threadIdx.x == 0) s_cnt = 0;
    __syncthreads();
    if (threadIdx.x < NBOX) {
        int lab = labels[b * NBOX + threadIdx.x];
        if (lab == c) {
            const float* bp = boxes + (size_t)(b * NBOX + threadIdx.x) * 4;
            float Wf = (float)W;
            int x = (int)floorf(bp[0] * Wf);
            int y = (int)floorf(bp[1] * Wf);
            float s2 = bp[2] * Wf + bp[3] * Wf;
            int r = (int)floorf(s2 * 0.25f);       // /4.0 exact as *0.25f
            if (r < 1) r = 1;
            float sigma = (float)(2 * r + 1) * (1.0f / 6.0f);
            int k = atomicAdd(&s_cnt, 1);
            s_x[k] = x; s_y[k] = y; s_r2[k] = r * r;
            s_inv[k] = 1.0f / (2.0f * sigma * sigma);
        }
    }
    __syncthreads();
    int nb = s_cnt;

    const float4* hp = (const float4*)(heat + (size_t)chan * (W * W) + base);
    float pA = 0.f, pB = 0.f, nA = 0.f, nB = 0.f; int npos = 0;

    if (nb == 0) {
        if (cat == 2) process_fast<1>(hp, nA, nB);
        else          process_fast<4>(hp, nA, nB);
    } else {
        if (cat == 0)      process_box<7,4>(hp, base, nb, s_x, s_y, s_r2, s_inv, pA, pB, nA, nB, npos);
        else if (cat == 1) process_box<6,4>(hp, base, nb, s_x, s_y, s_r2, s_inv, pA, pB, nA, nB, npos);
        else               process_box<5,1>(hp, base, nb, s_x, s_y, s_r2, s_inv, pA, pB, nA, nB, npos);
    }

    float pacc = SCALEf * (pA - pB);   // ln2/4 * sum[(lg2(arg)-1)*m]
    float nacc = SCALEf * (nA - nB);

    // ---- deterministic block reduction ----
    #pragma unroll
    for (int o = 16; o > 0; o >>= 1) {
        pacc += __shfl_down_sync(0xffffffffu, pacc, o);
        nacc += __shfl_down_sync(0xffffffffu, nacc, o);
        npos += __shfl_down_sync(0xffffffffu, npos, o);
    }
    __shared__ float sp[8], sn[8];
    __shared__ int   si[8];
    int wid = threadIdx.x >> 5, lane = threadIdx.x & 31;
    if (lane == 0) { sp[wid] = pacc; sn[wid] = nacc; si[wid] = npos; }
    __syncthreads();

    __shared__ int s_last;
    if (threadIdx.x == 0) {
        float P = 0.f, Ng = 0.f; int I = 0;
        #pragma unroll
        for (int i = 0; i < 8; i++) { P += sp[i]; Ng += sn[i]; I += si[i]; }
        g_pos[chan][slot] = P; g_neg[chan][slot] = Ng; g_np[chan][slot] = I;
        __threadfence();
        int prev = atomicAdd(&g_arrive, 1);
        s_last = (prev == NBLOCKS - 1);
    }
    __syncthreads();

    // ---- fused epilogue by the last-arriving block (fixed order, deterministic) ----
    if (s_last) {
        float acc = 0.f;
        for (int ch = threadIdx.x; ch < NCH; ch += THREADS) {
            float pl = 0.f, nl = 0.f; int np = 0;
            #pragma unroll
            for (int s = 0; s < 6; s++) {
                pl += __ldcg(&g_pos[ch][s]);
                nl += __ldcg(&g_neg[ch][s]);
                np += __ldcg(&g_np [ch][s]);
            }
            float loss = (np == 0) ? (-nl) : (-(pl + nl) / (float)np);
            acc += fminf(loss, 10.0f);
        }
        #pragma unroll
        for (int o = 16; o > 0; o >>= 1) acc += __shfl_down_sync(0xffffffffu, acc, o);
        __shared__ float sa[8];
        if (lane == 0) sa[wid] = acc;
        __syncthreads();
        if (threadIdx.x == 0) {
            float tot = 0.f;
            #pragma unroll
            for (int i = 0; i < 8; i++) tot += sa[i];
            float mean = tot * (1.0f / (float)NCH);
            float lm = log1pf(mean);
            out[0] = lm / (1.0f + lm);
            g_arrive = 0;   // reset for next graph replay
        }
    }
}

extern "C" void kernel_launch(void* const* d_in, const int* in_sizes, int n_in,
                              void* d_out, int out_size)
{
    const float* h0     = (const float*)d_in[0];   // [8,80,128,128]
    const float* h1     = (const float*)d_in[1];   // [8,80,64,64]
    const float* h2     = (const float*)d_in[2];   // [8,80,32,32]
    const float* boxes  = (const float*)d_in[3];   // [8,32,4]
    const int*   labels = (const int*)d_in[4];     // [8,32]
    // d_in[5] = image_sizes (int64) — cancels mathematically, unused.

    hough_main<<<NBLOCKS, THREADS>>>(h0, h1, h2, boxes, labels, (float*)d_out);
}